// round 2
// baseline (speedup 1.0000x reference)
#include <cuda_runtime.h>

#define NUM_HEADS    32
#define NUM_KV_HEADS 8
#define HEAD_DIM     128
#define WINDOW       512
#define NUM_META     4
#define BLOCK_M      32
#define TILE_N       64
#define NTHREADS     256

#define QSTRIDE (NUM_HEADS * HEAD_DIM)     // 4096 floats per token
#define KSTRIDE (NUM_KV_HEADS * HEAD_DIM)  // 1024 floats per token

// smem layout (floats):
//   [0,     4096)  sQT  [128][32]   (xor-swizzled transposed Q tile)
//   [4096, 12288)  sK   64 x 128
//   [12288,20480)  sV   64 x 128
//   [20480,22560)  sS   [32][65]    (scores / probabilities, padded)
#define SMEM_FLOATS (4096 + 8192 + 8192 + 32 * 65)

__global__ __launch_bounds__(NTHREADS, 2)
void swa_attn_kernel(const float* __restrict__ Q, const float* __restrict__ K,
                     const float* __restrict__ V, float* __restrict__ O)
{
    extern __shared__ float smem[];
    float*  sQT = smem;
    float4* sK4 = (float4*)(smem + 4096);
    float4* sV4 = (float4*)(smem + 12288);
    float*  sS  = smem + 20480;

    const int h    = blockIdx.y;
    const int i0   = blockIdx.x * BLOCK_M;
    const int kh   = h >> 2;                 // GQA: 4 q-heads per kv-head
    const int tid  = threadIdx.x;
    const int w    = tid >> 5;
    const int lane = tid & 31;

    const float NEG_INF = __int_as_float(0xff800000);
    const float scale   = 0.08838834764831845f;  // 1/sqrt(128)

    // ---- load Q tile, transposed + xor-swizzled (conflict-free reads in phase A)
    {
        const float* qbase = Q + (size_t)i0 * QSTRIDE + h * HEAD_DIM;
        for (int e = tid; e < BLOCK_M * HEAD_DIM; e += NTHREADS) {
            int m = e >> 7, d = e & 127;
            sQT[d * 32 + (m ^ (d & 31))] = qbase[(size_t)m * QSTRIDE + d];
        }
    }

    // per-warp persistent state: warp w owns q-rows w*4 .. w*4+3
    float acc[4][4];
    float m_run[4], l_run[4];
    #pragma unroll
    for (int rr = 0; rr < 4; rr++) {
        m_run[rr] = NEG_INF;
        l_run[rr] = 0.f;
        #pragma unroll
        for (int c = 0; c < 4; c++) acc[rr][c] = 0.f;
    }

    const int t_lo = max(0, i0 - WINDOW) / TILE_N;
    const int t_hi = (i0 + BLOCK_M - 1) / TILE_N;

    for (int tix = 0; ; tix++) {
        int t;
        if (t_lo == 0) t = tix;                          // window still covers meta
        else           t = (tix == 0) ? 0 : (t_lo + tix - 1);  // meta tile first, then window
        if (t > t_hi) break;
        const int j0 = t * TILE_N;

        __syncthreads();  // previous tile's smem readers done

        // ---- stage K/V tile (global -> smem), coalesced float4
        {
            const float4* K4 = (const float4*)K;
            const float4* V4 = (const float4*)V;
            const size_t base = (size_t)j0 * (KSTRIDE / 4) + (size_t)kh * (HEAD_DIM / 4);
            for (int e = tid; e < TILE_N * 32; e += NTHREADS) {
                int n = e >> 5, c = e & 31;
                size_t g = base + (size_t)n * (KSTRIDE / 4) + c;
                sK4[n * 32 + c] = K4[g];
                sV4[n * 32 + c] = V4[g];
            }
        }
        __syncthreads();

        // ---- Phase A: scores. warp w computes n = w*8..w*8+7, lane = q-row.
        {
            float s[8];
            #pragma unroll
            for (int n8 = 0; n8 < 8; n8++) s[n8] = 0.f;

            #pragma unroll
            for (int ch = 0; ch < 8; ch++) {
                float qreg[16];
                #pragma unroll
                for (int k = 0; k < 16; k++) {
                    int d = ch * 16 + k;
                    qreg[k] = sQT[d * 32 + (lane ^ (d & 31))];
                }
                #pragma unroll
                for (int n8 = 0; n8 < 8; n8++) {
                    const float4* krow = &sK4[(w * 8 + n8) * 32 + ch * 4];
                    #pragma unroll
                    for (int kk = 0; kk < 4; kk++) {
                        float4 kv = krow[kk];   // broadcast LDS.128
                        s[n8] += qreg[kk * 4 + 0] * kv.x + qreg[kk * 4 + 1] * kv.y
                               + qreg[kk * 4 + 2] * kv.z + qreg[kk * 4 + 3] * kv.w;
                    }
                }
            }

            const int i = i0 + lane;
            #pragma unroll
            for (int n8 = 0; n8 < 8; n8++) {
                int n = w * 8 + n8;
                int j = j0 + n;
                bool ok = (i >= j) && ((i - j) <= WINDOW || j < NUM_META);
                sS[lane * 65 + n] = ok ? s[n8] * scale : NEG_INF;
            }
        }
        __syncthreads();

        // ---- Phase B: online softmax + PV. warp w owns rows w*4..w*4+3.
        {
            #pragma unroll
            for (int rr = 0; rr < 4; rr++) {
                int row = w * 4 + rr;
                float sa = sS[row * 65 + lane];
                float sb = sS[row * 65 + lane + 32];
                float mx = fmaxf(sa, sb);
                #pragma unroll
                for (int off = 16; off > 0; off >>= 1)
                    mx = fmaxf(mx, __shfl_xor_sync(0xffffffffu, mx, off));
                float m_new = fmaxf(m_run[rr], mx);
                float alpha = (m_new == NEG_INF) ? 1.f : __expf(m_run[rr] - m_new);
                float pa = (sa == NEG_INF) ? 0.f : __expf(sa - m_new);
                float pb = (sb == NEG_INF) ? 0.f : __expf(sb - m_new);
                float ps = pa + pb;
                #pragma unroll
                for (int off = 16; off > 0; off >>= 1)
                    ps += __shfl_xor_sync(0xffffffffu, ps, off);
                l_run[rr] = l_run[rr] * alpha + ps;
                m_run[rr] = m_new;
                #pragma unroll
                for (int c = 0; c < 4; c++) acc[rr][c] *= alpha;
                sS[row * 65 + lane]      = pa;
                sS[row * 65 + lane + 32] = pb;
            }
            __syncwarp();

            #pragma unroll 8
            for (int n = 0; n < TILE_N; n++) {
                float4 v4 = sV4[n * 32 + lane];          // conflict-free LDS.128
                #pragma unroll
                for (int rr = 0; rr < 4; rr++) {
                    float p = sS[(w * 4 + rr) * 65 + n]; // broadcast
                    acc[rr][0] += p * v4.x;
                    acc[rr][1] += p * v4.y;
                    acc[rr][2] += p * v4.z;
                    acc[rr][3] += p * v4.w;
                }
            }
        }
    }

    // ---- epilogue: O[i, h*128 + lane*4 .. +3]
    #pragma unroll
    for (int rr = 0; rr < 4; rr++) {
        int i = i0 + w * 4 + rr;
        float inv = 1.0f / l_run[rr];
        float4 o;
        o.x = acc[rr][0] * inv;
        o.y = acc[rr][1] * inv;
        o.z = acc[rr][2] * inv;
        o.w = acc[rr][3] * inv;
        ((float4*)(O + (size_t)i * QSTRIDE + h * HEAD_DIM))[lane] = o;
    }
}

extern "C" void kernel_launch(void* const* d_in, const int* in_sizes, int n_in,
                              void* d_out, int out_size)
{
    const float* Q = (const float*)d_in[0];
    const float* K = (const float*)d_in[1];
    const float* V = (const float*)d_in[2];
    float* O = (float*)d_out;

    const int S = in_sizes[0] / QSTRIDE;   // 2048

    // idempotent; executes immediately even under graph capture
    cudaFuncSetAttribute(swa_attn_kernel,
                         cudaFuncAttributeMaxDynamicSharedMemorySize,
                         SMEM_FLOATS * 4);

    dim3 grid(S / BLOCK_M, NUM_HEADS);
    swa_attn_kernel<<<grid, NTHREADS, SMEM_FLOATS * 4>>>(Q, K, V, O);
}

// round 3
// speedup vs baseline: 1.0021x; 1.0021x over previous
#include <cuda_runtime.h>

#define NUM_HEADS    32
#define NUM_KV_HEADS 8
#define HEAD_DIM     128
#define WINDOW       512
#define NUM_META     4
#define BLOCK_M      32
#define TILE_N       64
#define NTHREADS     256

#define QSTRIDE (NUM_HEADS * HEAD_DIM)     // 4096 floats per token
#define KSTRIDE (NUM_KV_HEADS * HEAD_DIM)  // 1024 floats per token

// smem layout (floats):
//   [0,     4096)  sQT  [128][32]   (xor-swizzled transposed Q tile)
//   [4096, 12288)  sK   64 x 128
//   [12288,20480)  sV   64 x 128
//   [20480,22560)  sS   [32][65]    (scores / probabilities, padded)
#define SMEM_FLOATS (4096 + 8192 + 8192 + 32 * 65)

__global__ __launch_bounds__(NTHREADS, 2)
void swa_attn_kernel(const float* __restrict__ Q, const float* __restrict__ K,
                     const float* __restrict__ V, float* __restrict__ O)
{
    extern __shared__ float smem[];
    float*  sQT = smem;
    float4* sK4 = (float4*)(smem + 4096);
    float4* sV4 = (float4*)(smem + 12288);
    float*  sS  = smem + 20480;

    const int h    = blockIdx.y;
    const int i0   = blockIdx.x * BLOCK_M;
    const int kh   = h >> 2;                 // GQA: 4 q-heads per kv-head
    const int tid  = threadIdx.x;
    const int w    = tid >> 5;
    const int lane = tid & 31;

    const float NEG_INF = __int_as_float(0xff800000);
    const float scale   = 0.08838834764831845f;  // 1/sqrt(128)

    // ---- load Q tile, transposed + xor-swizzled (conflict-free reads in phase A)
    {
        const float* qbase = Q + (size_t)i0 * QSTRIDE + h * HEAD_DIM;
        for (int e = tid; e < BLOCK_M * HEAD_DIM; e += NTHREADS) {
            int m = e >> 7, d = e & 127;
            sQT[d * 32 + (m ^ (d & 31))] = qbase[(size_t)m * QSTRIDE + d];
        }
    }

    // per-warp persistent state: warp w owns q-rows w*4 .. w*4+3
    float acc[4][4];
    float m_run[4], l_run[4];
    #pragma unroll
    for (int rr = 0; rr < 4; rr++) {
        m_run[rr] = NEG_INF;
        l_run[rr] = 0.f;
        #pragma unroll
        for (int c = 0; c < 4; c++) acc[rr][c] = 0.f;
    }

    const int t_lo = max(0, i0 - WINDOW) / TILE_N;
    const int t_hi = (i0 + BLOCK_M - 1) / TILE_N;

    for (int tix = 0; ; tix++) {
        int t;
        if (t_lo == 0) t = tix;                          // window still covers meta
        else           t = (tix == 0) ? 0 : (t_lo + tix - 1);  // meta tile first, then window
        if (t > t_hi) break;
        const int j0 = t * TILE_N;

        __syncthreads();  // previous tile's smem readers done

        // ---- stage K/V tile (global -> smem), coalesced float4
        {
            const float4* K4 = (const float4*)K;
            const float4* V4 = (const float4*)V;
            const size_t base = (size_t)j0 * (KSTRIDE / 4) + (size_t)kh * (HEAD_DIM / 4);
            for (int e = tid; e < TILE_N * 32; e += NTHREADS) {
                int n = e >> 5, c = e & 31;
                size_t g = base + (size_t)n * (KSTRIDE / 4) + c;
                sK4[n * 32 + c] = K4[g];
                sV4[n * 32 + c] = V4[g];
            }
        }
        __syncthreads();

        // ---- Phase A: scores. warp w computes n = w*8..w*8+7, lane = q-row.
        {
            float s[8];
            #pragma unroll
            for (int n8 = 0; n8 < 8; n8++) s[n8] = 0.f;

            #pragma unroll
            for (int ch = 0; ch < 8; ch++) {
                float qreg[16];
                #pragma unroll
                for (int k = 0; k < 16; k++) {
                    int d = ch * 16 + k;
                    qreg[k] = sQT[d * 32 + (lane ^ (d & 31))];
                }
                #pragma unroll
                for (int n8 = 0; n8 < 8; n8++) {
                    const float4* krow = &sK4[(w * 8 + n8) * 32 + ch * 4];
                    #pragma unroll
                    for (int kk = 0; kk < 4; kk++) {
                        float4 kv = krow[kk];   // broadcast LDS.128
                        s[n8] += qreg[kk * 4 + 0] * kv.x + qreg[kk * 4 + 1] * kv.y
                               + qreg[kk * 4 + 2] * kv.z + qreg[kk * 4 + 3] * kv.w;
                    }
                }
            }

            const int i = i0 + lane;
            #pragma unroll
            for (int n8 = 0; n8 < 8; n8++) {
                int n = w * 8 + n8;
                int j = j0 + n;
                bool ok = (i >= j) && ((i - j) <= WINDOW || j < NUM_META);
                sS[lane * 65 + n] = ok ? s[n8] * scale : NEG_INF;
            }
        }
        __syncthreads();

        // ---- Phase B: online softmax + PV. warp w owns rows w*4..w*4+3.
        {
            #pragma unroll
            for (int rr = 0; rr < 4; rr++) {
                int row = w * 4 + rr;
                float sa = sS[row * 65 + lane];
                float sb = sS[row * 65 + lane + 32];
                float mx = fmaxf(sa, sb);
                #pragma unroll
                for (int off = 16; off > 0; off >>= 1)
                    mx = fmaxf(mx, __shfl_xor_sync(0xffffffffu, mx, off));
                float m_new = fmaxf(m_run[rr], mx);
                float alpha = (m_new == NEG_INF) ? 1.f : __expf(m_run[rr] - m_new);
                float pa = (sa == NEG_INF) ? 0.f : __expf(sa - m_new);
                float pb = (sb == NEG_INF) ? 0.f : __expf(sb - m_new);
                float ps = pa + pb;
                #pragma unroll
                for (int off = 16; off > 0; off >>= 1)
                    ps += __shfl_xor_sync(0xffffffffu, ps, off);
                l_run[rr] = l_run[rr] * alpha + ps;
                m_run[rr] = m_new;
                #pragma unroll
                for (int c = 0; c < 4; c++) acc[rr][c] *= alpha;
                sS[row * 65 + lane]      = pa;
                sS[row * 65 + lane + 32] = pb;
            }
            __syncwarp();

            #pragma unroll 8
            for (int n = 0; n < TILE_N; n++) {
                float4 v4 = sV4[n * 32 + lane];          // conflict-free LDS.128
                #pragma unroll
                for (int rr = 0; rr < 4; rr++) {
                    float p = sS[(w * 4 + rr) * 65 + n]; // broadcast
                    acc[rr][0] += p * v4.x;
                    acc[rr][1] += p * v4.y;
                    acc[rr][2] += p * v4.z;
                    acc[rr][3] += p * v4.w;
                }
            }
        }
    }

    // ---- epilogue: O[i, h*128 + lane*4 .. +3]
    #pragma unroll
    for (int rr = 0; rr < 4; rr++) {
        int i = i0 + w * 4 + rr;
        float inv = 1.0f / l_run[rr];
        float4 o;
        o.x = acc[rr][0] * inv;
        o.y = acc[rr][1] * inv;
        o.z = acc[rr][2] * inv;
        o.w = acc[rr][3] * inv;
        ((float4*)(O + (size_t)i * QSTRIDE + h * HEAD_DIM))[lane] = o;
    }
}

extern "C" void kernel_launch(void* const* d_in, const int* in_sizes, int n_in,
                              void* d_out, int out_size)
{
    const float* Q = (const float*)d_in[0];
    const float* K = (const float*)d_in[1];
    const float* V = (const float*)d_in[2];
    float* O = (float*)d_out;

    const int S = in_sizes[0] / QSTRIDE;   // 2048

    // idempotent; executes immediately even under graph capture
    cudaFuncSetAttribute(swa_attn_kernel,
                         cudaFuncAttributeMaxDynamicSharedMemorySize,
                         SMEM_FLOATS * 4);

    dim3 grid(S / BLOCK_M, NUM_HEADS);
    swa_attn_kernel<<<grid, NTHREADS, SMEM_FLOATS * 4>>>(Q, K, V, O);
}

// round 4
// speedup vs baseline: 1.0027x; 1.0006x over previous
#include <cuda_runtime.h>

#define NUM_HEADS    32
#define NUM_KV_HEADS 8
#define HEAD_DIM     128
#define WINDOW       512
#define NUM_META     4
#define BLOCK_M      32
#define TILE_N       64
#define NTHREADS     256

#define QSTRIDE (NUM_HEADS * HEAD_DIM)     // 4096 floats per token
#define KSTRIDE (NUM_KV_HEADS * HEAD_DIM)  // 1024 floats per token

// smem layout (floats):
//   [0,     4096)  sQT  [128][32]   (xor-swizzled transposed Q tile)
//   [4096, 12288)  sK   64 x 128
//   [12288,20480)  sV   64 x 128
//   [20480,22560)  sS   [32][65]    (scores / probabilities, padded)
#define SMEM_FLOATS (4096 + 8192 + 8192 + 32 * 65)

__global__ __launch_bounds__(NTHREADS, 2)
void swa_attn_kernel(const float* __restrict__ Q, const float* __restrict__ K,
                     const float* __restrict__ V, float* __restrict__ O)
{
    extern __shared__ float smem[];
    float*  sQT = smem;
    float4* sK4 = (float4*)(smem + 4096);
    float4* sV4 = (float4*)(smem + 12288);
    float*  sS  = smem + 20480;

    const int h    = blockIdx.y;
    const int i0   = blockIdx.x * BLOCK_M;
    const int kh   = h >> 2;                 // GQA: 4 q-heads per kv-head
    const int tid  = threadIdx.x;
    const int w    = tid >> 5;
    const int lane = tid & 31;

    const float NEG_INF = __int_as_float(0xff800000);
    const float scale   = 0.08838834764831845f;  // 1/sqrt(128)

    // ---- load Q tile, transposed + xor-swizzled (conflict-free reads in phase A)
    {
        const float* qbase = Q + (size_t)i0 * QSTRIDE + h * HEAD_DIM;
        for (int e = tid; e < BLOCK_M * HEAD_DIM; e += NTHREADS) {
            int m = e >> 7, d = e & 127;
            sQT[d * 32 + (m ^ (d & 31))] = qbase[(size_t)m * QSTRIDE + d];
        }
    }

    // per-warp persistent state: warp w owns q-rows w*4 .. w*4+3
    float acc[4][4];
    float m_run[4], l_run[4];
    #pragma unroll
    for (int rr = 0; rr < 4; rr++) {
        m_run[rr] = NEG_INF;
        l_run[rr] = 0.f;
        #pragma unroll
        for (int c = 0; c < 4; c++) acc[rr][c] = 0.f;
    }

    const int t_lo = max(0, i0 - WINDOW) / TILE_N;
    const int t_hi = (i0 + BLOCK_M - 1) / TILE_N;

    for (int tix = 0; ; tix++) {
        int t;
        if (t_lo == 0) t = tix;                          // window still covers meta
        else           t = (tix == 0) ? 0 : (t_lo + tix - 1);  // meta tile first, then window
        if (t > t_hi) break;
        const int j0 = t * TILE_N;

        __syncthreads();  // previous tile's smem readers done

        // ---- stage K/V tile (global -> smem), coalesced float4
        {
            const float4* K4 = (const float4*)K;
            const float4* V4 = (const float4*)V;
            const size_t base = (size_t)j0 * (KSTRIDE / 4) + (size_t)kh * (HEAD_DIM / 4);
            for (int e = tid; e < TILE_N * 32; e += NTHREADS) {
                int n = e >> 5, c = e & 31;
                size_t g = base + (size_t)n * (KSTRIDE / 4) + c;
                sK4[n * 32 + c] = K4[g];
                sV4[n * 32 + c] = V4[g];
            }
        }
        __syncthreads();

        // ---- Phase A: scores. warp w computes n = w*8..w*8+7, lane = q-row.
        {
            float s[8];
            #pragma unroll
            for (int n8 = 0; n8 < 8; n8++) s[n8] = 0.f;

            #pragma unroll
            for (int ch = 0; ch < 8; ch++) {
                float qreg[16];
                #pragma unroll
                for (int k = 0; k < 16; k++) {
                    int d = ch * 16 + k;
                    qreg[k] = sQT[d * 32 + (lane ^ (d & 31))];
                }
                #pragma unroll
                for (int n8 = 0; n8 < 8; n8++) {
                    const float4* krow = &sK4[(w * 8 + n8) * 32 + ch * 4];
                    #pragma unroll
                    for (int kk = 0; kk < 4; kk++) {
                        float4 kv = krow[kk];   // broadcast LDS.128
                        s[n8] += qreg[kk * 4 + 0] * kv.x + qreg[kk * 4 + 1] * kv.y
                               + qreg[kk * 4 + 2] * kv.z + qreg[kk * 4 + 3] * kv.w;
                    }
                }
            }

            const int i = i0 + lane;
            #pragma unroll
            for (int n8 = 0; n8 < 8; n8++) {
                int n = w * 8 + n8;
                int j = j0 + n;
                bool ok = (i >= j) && ((i - j) <= WINDOW || j < NUM_META);
                sS[lane * 65 + n] = ok ? s[n8] * scale : NEG_INF;
            }
        }
        __syncthreads();

        // ---- Phase B: online softmax + PV. warp w owns rows w*4..w*4+3.
        {
            #pragma unroll
            for (int rr = 0; rr < 4; rr++) {
                int row = w * 4 + rr;
                float sa = sS[row * 65 + lane];
                float sb = sS[row * 65 + lane + 32];
                float mx = fmaxf(sa, sb);
                #pragma unroll
                for (int off = 16; off > 0; off >>= 1)
                    mx = fmaxf(mx, __shfl_xor_sync(0xffffffffu, mx, off));
                float m_new = fmaxf(m_run[rr], mx);
                float alpha = (m_new == NEG_INF) ? 1.f : __expf(m_run[rr] - m_new);
                float pa = (sa == NEG_INF) ? 0.f : __expf(sa - m_new);
                float pb = (sb == NEG_INF) ? 0.f : __expf(sb - m_new);
                float ps = pa + pb;
                #pragma unroll
                for (int off = 16; off > 0; off >>= 1)
                    ps += __shfl_xor_sync(0xffffffffu, ps, off);
                l_run[rr] = l_run[rr] * alpha + ps;
                m_run[rr] = m_new;
                #pragma unroll
                for (int c = 0; c < 4; c++) acc[rr][c] *= alpha;
                sS[row * 65 + lane]      = pa;
                sS[row * 65 + lane + 32] = pb;
            }
            __syncwarp();

            #pragma unroll 8
            for (int n = 0; n < TILE_N; n++) {
                float4 v4 = sV4[n * 32 + lane];          // conflict-free LDS.128
                #pragma unroll
                for (int rr = 0; rr < 4; rr++) {
                    float p = sS[(w * 4 + rr) * 65 + n]; // broadcast
                    acc[rr][0] += p * v4.x;
                    acc[rr][1] += p * v4.y;
                    acc[rr][2] += p * v4.z;
                    acc[rr][3] += p * v4.w;
                }
            }
        }
    }

    // ---- epilogue: O[i, h*128 + lane*4 .. +3]
    #pragma unroll
    for (int rr = 0; rr < 4; rr++) {
        int i = i0 + w * 4 + rr;
        float inv = 1.0f / l_run[rr];
        float4 o;
        o.x = acc[rr][0] * inv;
        o.y = acc[rr][1] * inv;
        o.z = acc[rr][2] * inv;
        o.w = acc[rr][3] * inv;
        ((float4*)(O + (size_t)i * QSTRIDE + h * HEAD_DIM))[lane] = o;
    }
}

extern "C" void kernel_launch(void* const* d_in, const int* in_sizes, int n_in,
                              void* d_out, int out_size)
{
    const float* Q = (const float*)d_in[0];
    const float* K = (const float*)d_in[1];
    const float* V = (const float*)d_in[2];
    float* O = (float*)d_out;

    const int S = in_sizes[0] / QSTRIDE;   // 2048

    // idempotent; executes immediately even under graph capture
    cudaFuncSetAttribute(swa_attn_kernel,
                         cudaFuncAttributeMaxDynamicSharedMemorySize,
                         SMEM_FLOATS * 4);

    dim3 grid(S / BLOCK_M, NUM_HEADS);
    swa_attn_kernel<<<grid, NTHREADS, SMEM_FLOATS * 4>>>(Q, K, V, O);
}

// round 5
// speedup vs baseline: 1.0908x; 1.0879x over previous
#include <cuda_runtime.h>
#include <cstdint>

#define NUM_HEADS    32
#define NUM_KV_HEADS 8
#define HEAD_DIM     128
#define WINDOW       512
#define NUM_META     4
#define BLOCK_M      64
#define TILE_N       64
#define NTHREADS     256

#define QSTRIDE (NUM_HEADS * HEAD_DIM)     // 4096
#define KSTRIDE (NUM_KV_HEADS * HEAD_DIM)  // 1024

// shared memory layout (float offsets)
#define OFF_QT 0                       // [128][64]  QT[d][m]
#define OFF_KT (OFF_QT + 128 * 64)     // [128][64]  KT[d][n]
#define OFF_V  (OFF_KT + 128 * 64)     // [64][132]  V[n][d] (padded pitch)
#define OFF_PT (OFF_V + 64 * 132)      // [64][64]   PT[n][m^swz(n)]
#define OFF_AL (OFF_PT + 64 * 64)      // alpha[64]
#define OFF_L  (OFF_AL + 64)           // l[64]
#define SMEM_FLOATS (OFF_L + 64)       // 29056 floats = 113.5 KiB

// ---- packed fp32x2 helpers ----
__device__ __forceinline__ unsigned long long pack2(float x) {
    unsigned long long r; unsigned u = __float_as_uint(x);
    asm("mov.b64 %0, {%1, %1};" : "=l"(r) : "r"(u));
    return r;
}
__device__ __forceinline__ void unpack2(unsigned long long p, float& lo, float& hi) {
    unsigned a, b;
    asm("mov.b64 {%0, %1}, %2;" : "=r"(a), "=r"(b) : "l"(p));
    lo = __uint_as_float(a); hi = __uint_as_float(b);
}
#define FFMA2(d_, a_, b_) asm("fma.rn.f32x2 %0, %1, %2, %0;" : "+l"(d_) : "l"(a_), "l"(b_))
#define FMUL2(d_, a_, b_) asm("mul.rn.f32x2 %0, %1, %2;" : "=l"(d_) : "l"(a_), "l"(b_))

__global__ __launch_bounds__(NTHREADS, 2)
void swa_attn_kernel(const float* __restrict__ Q, const float* __restrict__ K,
                     const float* __restrict__ V, float* __restrict__ O)
{
    extern __shared__ float sm[];
    float* sQT = sm + OFF_QT;
    float* sKT = sm + OFF_KT;
    float* sV  = sm + OFF_V;
    float* sPT = sm + OFF_PT;
    float* sAL = sm + OFF_AL;
    float* sL  = sm + OFF_L;

    const int h   = blockIdx.y;
    const int i0  = (gridDim.x - 1 - (int)blockIdx.x) * BLOCK_M;  // heavy blocks first
    const int kh  = h >> 2;
    const int tid = threadIdx.x;
    const int lane = tid & 31;

    // phase-A tiling: thread = (mbA, nbA); 4 m-rows (2 pairs) x 4 n-cols
    const int mbA = tid >> 4;        // 0..15
    const int nbA = tid & 15;        // 0..15
    const int m0A = mbA * 4;
    const int n0A = nbA * 4;
    // phase-B tiling: warp owns 8 m-rows (4 pairs), lane owns 4 d
    const int mB0 = (tid >> 5) * 8;
    const int dB  = lane * 4;

    const float SCALE = 0.08838834764831845f;  // 1/sqrt(128)

    // ---- build QT[d][m] (transposed). lanes span m -> conflict-free STS.
    {
        const float4* Qv = (const float4*)(Q + (size_t)i0 * QSTRIDE + h * HEAD_DIM);
        #pragma unroll
        for (int it = 0; it < 8; it++) {
            int e = tid + it * NTHREADS;       // 0..2047
            int m = e & 63, c = e >> 6;        // c: float4 column 0..31
            float4 q4 = Qv[(size_t)m * (QSTRIDE / 4) + c];
            int d = c * 4;
            sQT[(d + 0) * 64 + m] = q4.x;
            sQT[(d + 1) * 64 + m] = q4.y;
            sQT[(d + 2) * 64 + m] = q4.z;
            sQT[(d + 3) * 64 + m] = q4.w;
        }
    }

    float m_run[4], l_run[4];
    #pragma unroll
    for (int r = 0; r < 4; r++) { m_run[r] = -1e30f; l_run[r] = 0.f; }

    unsigned long long acc[4][4];   // [m-pair][d] packed (m even, m odd)
    #pragma unroll
    for (int a = 0; a < 4; a++)
        #pragma unroll
        for (int b = 0; b < 4; b++) acc[a][b] = 0ull;

    const int t_lo = (i0 > WINDOW) ? ((i0 - WINDOW) >> 6) : 0;
    const int t_hi = i0 >> 6;
    const int ntiles = (t_lo == 0) ? (t_hi + 1) : (t_hi - t_lo + 2);

    for (int tix = 0; tix < ntiles; tix++) {
        const int t  = (t_lo == 0) ? tix : ((tix == 0) ? 0 : (t_lo + tix - 1));
        const int j0 = t << 6;
        const bool meta_only = (t == 0) && (t_lo >= 1);  // window moved past meta tile

        __syncthreads();  // prev tile's readers done before restaging

        // ---- stage KT (transposed) + V. lanes span n -> conflict-free STS.
        {
            const float4* K4 = (const float4*)(K + (size_t)j0 * KSTRIDE + kh * HEAD_DIM);
            const float4* V4 = (const float4*)(V + (size_t)j0 * KSTRIDE + kh * HEAD_DIM);
            #pragma unroll
            for (int it = 0; it < 8; it++) {
                int e = tid + it * NTHREADS;
                int n = e & 63, c = e >> 6;
                size_t g = (size_t)n * (KSTRIDE / 4) + c;
                float4 k4 = K4[g];
                float4 v4 = V4[g];
                int d = c * 4;
                sKT[(d + 0) * 64 + n] = k4.x;
                sKT[(d + 1) * 64 + n] = k4.y;
                sKT[(d + 2) * 64 + n] = k4.z;
                sKT[(d + 3) * 64 + n] = k4.w;
                *(float4*)&sV[n * 132 + d] = v4;
            }
        }
        __syncthreads();

        // ---- phase A: S = Q K^T, packed over m-pairs
        unsigned long long s[2][4];
        #pragma unroll
        for (int a = 0; a < 2; a++)
            #pragma unroll
            for (int b = 0; b < 4; b++) s[a][b] = 0ull;

        {
            const float* qp = sQT + m0A;
            const float* kp = sKT + n0A;
            #pragma unroll 4
            for (int d = 0; d < 128; d++) {
                ulonglong2 qa = *(const ulonglong2*)(qp + d * 64); // (m0,m1),(m2,m3)
                float4 kv = *(const float4*)(kp + d * 64);
                unsigned long long k0 = pack2(kv.x), k1 = pack2(kv.y);
                unsigned long long k2 = pack2(kv.z), k3 = pack2(kv.w);
                FFMA2(s[0][0], qa.x, k0); FFMA2(s[0][1], qa.x, k1);
                FFMA2(s[0][2], qa.x, k2); FFMA2(s[0][3], qa.x, k3);
                FFMA2(s[1][0], qa.y, k0); FFMA2(s[1][1], qa.y, k1);
                FFMA2(s[1][2], qa.y, k2); FFMA2(s[1][3], qa.y, k3);
            }
        }

        // ---- mask + scale + online softmax (16 row-mate threads per m-row)
        float p[4][4];
        #pragma unroll
        for (int mp = 0; mp < 2; mp++)
            #pragma unroll
            for (int nj = 0; nj < 4; nj++) {
                float lo, hi; unpack2(s[mp][nj], lo, hi);
                int j   = j0 + n0A + nj;
                int ilo = i0 + m0A + 2 * mp;
                bool ok0 = (ilo     >= j) && (((ilo     - j) <= WINDOW) || (j < NUM_META));
                bool ok1 = (ilo + 1 >= j) && (((ilo + 1 - j) <= WINDOW) || (j < NUM_META));
                p[2 * mp    ][nj] = ok0 ? lo * SCALE : -1e30f;
                p[2 * mp + 1][nj] = ok1 ? hi * SCALE : -1e30f;
            }

        #pragma unroll
        for (int r = 0; r < 4; r++) {
            float mx = fmaxf(fmaxf(p[r][0], p[r][1]), fmaxf(p[r][2], p[r][3]));
            #pragma unroll
            for (int o = 8; o; o >>= 1) mx = fmaxf(mx, __shfl_xor_sync(0xffffffffu, mx, o));
            float m_new = fmaxf(m_run[r], mx);
            float al = __expf(m_run[r] - m_new);
            float ps = 0.f;
            #pragma unroll
            for (int nj = 0; nj < 4; nj++) { p[r][nj] = __expf(p[r][nj] - m_new); ps += p[r][nj]; }
            #pragma unroll
            for (int o = 8; o; o >>= 1) ps += __shfl_xor_sync(0xffffffffu, ps, o);
            l_run[r] = l_run[r] * al + ps;
            m_run[r] = m_new;
            if (nbA == 0) sAL[m0A + r] = al;
        }

        // ---- write P transposed, XOR-swizzled on m (conflict-free STS.128)
        {
            int swz = (nbA & 7) << 2;                // depends on n>>2 = nbA
            float* pt = sPT + (m0A ^ swz);
            #pragma unroll
            for (int nj = 0; nj < 4; nj++) {
                float4 v4; v4.x = p[0][nj]; v4.y = p[1][nj]; v4.z = p[2][nj]; v4.w = p[3][nj];
                *(float4*)&pt[(n0A + nj) * 64] = v4;
            }
        }
        __syncthreads();

        // ---- phase B: rescale acc by alpha, then acc += P^T V
        #pragma unroll
        for (int k = 0; k < 4; k++) {
            unsigned long long ap = *(const unsigned long long*)&sAL[mB0 + 2 * k];
            FMUL2(acc[k][0], acc[k][0], ap);
            FMUL2(acc[k][1], acc[k][1], ap);
            FMUL2(acc[k][2], acc[k][2], ap);
            FMUL2(acc[k][3], acc[k][3], ap);
        }

        const int n_end = meta_only ? NUM_META : TILE_N;
        const float* vp = sV + dB;
        #pragma unroll 2
        for (int n = 0; n < n_end; n++) {
            int swz = ((n >> 2) & 7) << 2;
            ulonglong2 pp0 = *(const ulonglong2*)&sPT[n * 64 + (mB0 ^ swz)];       // (m0,m1),(m2,m3)
            ulonglong2 pp1 = *(const ulonglong2*)&sPT[n * 64 + ((mB0 + 4) ^ swz)]; // (m4,m5),(m6,m7)
            float4 v4 = *(const float4*)(vp + n * 132);
            unsigned long long v0 = pack2(v4.x), v1 = pack2(v4.y);
            unsigned long long v2 = pack2(v4.z), v3 = pack2(v4.w);
            FFMA2(acc[0][0], pp0.x, v0); FFMA2(acc[0][1], pp0.x, v1);
            FFMA2(acc[0][2], pp0.x, v2); FFMA2(acc[0][3], pp0.x, v3);
            FFMA2(acc[1][0], pp0.y, v0); FFMA2(acc[1][1], pp0.y, v1);
            FFMA2(acc[1][2], pp0.y, v2); FFMA2(acc[1][3], pp0.y, v3);
            FFMA2(acc[2][0], pp1.x, v0); FFMA2(acc[2][1], pp1.x, v1);
            FFMA2(acc[2][2], pp1.x, v2); FFMA2(acc[2][3], pp1.x, v3);
            FFMA2(acc[3][0], pp1.y, v0); FFMA2(acc[3][1], pp1.y, v1);
            FFMA2(acc[3][2], pp1.y, v2); FFMA2(acc[3][3], pp1.y, v3);
        }
    }

    // ---- epilogue
    if (nbA == 0) {
        #pragma unroll
        for (int r = 0; r < 4; r++) sL[m0A + r] = l_run[r];
    }
    __syncthreads();

    #pragma unroll
    for (int k = 0; k < 4; k++) {
        float il0 = 1.0f / sL[mB0 + 2 * k];
        float il1 = 1.0f / sL[mB0 + 2 * k + 1];
        float4 o0, o1; float lo, hi;
        unpack2(acc[k][0], lo, hi); o0.x = lo * il0; o1.x = hi * il1;
        unpack2(acc[k][1], lo, hi); o0.y = lo * il0; o1.y = hi * il1;
        unpack2(acc[k][2], lo, hi); o0.z = lo * il0; o1.z = hi * il1;
        unpack2(acc[k][3], lo, hi); o0.w = lo * il0; o1.w = hi * il1;
        size_t row = (size_t)(i0 + mB0 + 2 * k) * QSTRIDE + h * HEAD_DIM + dB;
        *(float4*)(O + row)           = o0;
        *(float4*)(O + row + QSTRIDE) = o1;
    }
}

extern "C" void kernel_launch(void* const* d_in, const int* in_sizes, int n_in,
                              void* d_out, int out_size)
{
    const float* Q = (const float*)d_in[0];
    const float* K = (const float*)d_in[1];
    const float* V = (const float*)d_in[2];
    float* O = (float*)d_out;

    const int S = in_sizes[0] / QSTRIDE;   // 2048

    cudaFuncSetAttribute(swa_attn_kernel,
                         cudaFuncAttributeMaxDynamicSharedMemorySize,
                         SMEM_FLOATS * 4);

    dim3 grid(S / BLOCK_M, NUM_HEADS);
    swa_attn_kernel<<<grid, NTHREADS, SMEM_FLOATS * 4>>>(Q, K, V, O);
}